// round 4
// baseline (speedup 1.0000x reference)
#include <cuda_runtime.h>
#include <math.h>

#define NUM_USERS 8192
#define NUM_ITEMS 32768
#define FEAT      129
#define KP        132     // K padded to multiple of 4 (and of BK)
#define BM        128
#define BN        128
#define BK        44      // 3 chunks of 44 cover KP=132
#define SMP       132     // smem row pitch (BM + 4): keeps 16B alignment, spreads banks
#define TM        8
#define TN        8

// Scratch (static __device__ arrays: allocation-free per harness rules)
__device__ float g_A[NUM_USERS * KP];   // users, K-padded
__device__ float g_B[NUM_ITEMS * KP];   // items, sign-folded (d=0 negated), K-padded

__global__ void prep_kernel(const float* __restrict__ h) {
    int idx = blockIdx.x * blockDim.x + threadIdx.x;
    const int totalA = NUM_USERS * KP;
    const int totalB = NUM_ITEMS * KP;
    if (idx < totalA) {
        int m = idx / KP, k = idx - m * KP;
        g_A[idx] = (k < FEAT) ? h[m * FEAT + k] : 0.0f;
    } else if (idx < totalA + totalB) {
        int j = idx - totalA;
        int i = j / KP, k = j - i * KP;
        float v = (k < FEAT) ? h[(NUM_USERS + i) * FEAT + k] : 0.0f;
        if (k == 0) v = -v;   // fold sign vector into item features
        g_B[j] = v;
    }
}

__global__ __launch_bounds__(256, 2)
void gemm_acosh_kernel(float* __restrict__ out) {
    // smem: [k][m] layout, pitch SMP=132 floats -> row base k*528B is 16B-aligned
    __shared__ float As[BK][SMP];
    __shared__ float Bs[BK][SMP];

    const int m0 = blockIdx.y * BM;
    const int n0 = blockIdx.x * BN;
    const int tid = threadIdx.x;
    const int tx = tid & 15;   // n direction
    const int ty = tid >> 4;   // m direction

    float acc[TM][TN];
    #pragma unroll
    for (int i = 0; i < TM; i++)
        #pragma unroll
        for (int j = 0; j < TN; j++) acc[i][j] = 0.0f;

    // 3 K-chunks of 44
    for (int k0 = 0; k0 < KP; k0 += BK) {
        // Fill As: 128 rows x 11 float4 (44 floats) each, transposed into [k][m].
        // t -> (row = t/11, f4 = t%11): consecutive threads walk a row (coalesced).
        #pragma unroll 2
        for (int t = tid; t < BM * (BK / 4); t += 256) {
            int row = t / (BK / 4);
            int f4  = t - row * (BK / 4);
            const float4 v = *(const float4*)&g_A[(size_t)(m0 + row) * KP + k0 + f4 * 4];
            int kk = f4 * 4;
            As[kk + 0][row] = v.x;
            As[kk + 1][row] = v.y;
            As[kk + 2][row] = v.z;
            As[kk + 3][row] = v.w;
        }
        #pragma unroll 2
        for (int t = tid; t < BN * (BK / 4); t += 256) {
            int row = t / (BK / 4);
            int f4  = t - row * (BK / 4);
            const float4 v = *(const float4*)&g_B[(size_t)(n0 + row) * KP + k0 + f4 * 4];
            int kk = f4 * 4;
            Bs[kk + 0][row] = v.x;
            Bs[kk + 1][row] = v.y;
            Bs[kk + 2][row] = v.z;
            Bs[kk + 3][row] = v.w;
        }
        __syncthreads();

        #pragma unroll 4
        for (int k = 0; k < BK; ++k) {
            float a[TM], b[TN];
            const float4 a0 = *(const float4*)&As[k][ty * TM];
            const float4 a1 = *(const float4*)&As[k][ty * TM + 4];
            const float4 b0 = *(const float4*)&Bs[k][tx * TN];
            const float4 b1 = *(const float4*)&Bs[k][tx * TN + 4];
            a[0]=a0.x; a[1]=a0.y; a[2]=a0.z; a[3]=a0.w;
            a[4]=a1.x; a[5]=a1.y; a[6]=a1.z; a[7]=a1.w;
            b[0]=b0.x; b[1]=b0.y; b[2]=b0.z; b[3]=b0.w;
            b[4]=b1.x; b[5]=b1.y; b[6]=b1.z; b[7]=b1.w;
            #pragma unroll
            for (int i = 0; i < TM; i++)
                #pragma unroll
                for (int j = 0; j < TN; j++)
                    acc[i][j] = fmaf(a[i], b[j], acc[i][j]);
        }
        __syncthreads();
    }

    // Fused epilogue: theta = max(-prod, 1+1e-7); out = -min(acosh(theta)^2, 50)
    const float THMIN = 1.0f + 1e-7f;  // rounds to 1.00000011920928955f, same as jnp fp32
    #pragma unroll
    for (int i = 0; i < TM; i++) {
        float vals[TN];
        #pragma unroll
        for (int j = 0; j < TN; j++) {
            float theta = fmaxf(-acc[i][j], THMIN);
            float s = acoshf(theta);
            float sq = fminf(s * s, 50.0f);
            vals[j] = -sq;
        }
        const int u = m0 + ty * TM + i;
        float* outp = out + (size_t)u * NUM_ITEMS + n0 + tx * TN;
        *(float4*)(outp)     = make_float4(vals[0], vals[1], vals[2], vals[3]);
        *(float4*)(outp + 4) = make_float4(vals[4], vals[5], vals[6], vals[7]);
    }
}

extern "C" void kernel_launch(void* const* d_in, const int* in_sizes, int n_in,
                              void* d_out, int out_size) {
    const float* h = (const float*)d_in[0];
    float* out = (float*)d_out;

    const int totalPrep = NUM_USERS * KP + NUM_ITEMS * KP;
    prep_kernel<<<(totalPrep + 255) / 256, 256>>>(h);

    dim3 grid(NUM_ITEMS / BN, NUM_USERS / BM);  // (256, 64)
    gemm_acosh_kernel<<<grid, 256>>>(out);
}

// round 8
// speedup vs baseline: 2.5233x; 2.5233x over previous
#include <cuda_runtime.h>
#include <cuda_bf16.h>
#include <cstdint>
#include <math.h>

#define NUM_USERS 8192
#define NUM_ITEMS 32768
#define FEAT      129
#define KSEG      144              // one split segment, padded to mult of 16
#define KCAT      448              // 3*KSEG = 432, padded to 7 chunks of 64
#define KCHUNKS   7
#define BM        128
#define BN        256
#define BK        64
#define NTHREADS  512

// ---- scratch (__device__ globals: allocation-free) ----
__device__ __align__(128) __nv_bfloat16 g_Abf[(size_t)NUM_USERS * KCAT];  // [Ahi|Ahi|Alo|pad0]
__device__ __align__(128) __nv_bfloat16 g_Bbf[(size_t)NUM_ITEMS * KCAT];  // [Bhi|Blo|Bhi|pad0]

__device__ __forceinline__ uint32_t smem_u32(const void* p) {
    uint32_t a;
    asm("{ .reg .u64 t; cvta.to.shared.u64 t, %1; cvt.u32.u64 %0, t; }" : "=r"(a) : "l"(p));
    return a;
}

// ---- prep: fold sign, split fp32 -> (hi, lo) bf16, build concatenated-K operands ----
__global__ void prep_kernel(const float* __restrict__ h) {
    int idx = blockIdx.x * blockDim.x + threadIdx.x;
    const int totA = NUM_USERS * KSEG;
    const int totB = NUM_ITEMS * KSEG;
    const int totP = (NUM_USERS + NUM_ITEMS) * (KCAT - 3 * KSEG);  // zero pad cols 432..447
    if (idx < totA) {
        int u = idx / KSEG, k = idx - u * KSEG;
        float a = (k < FEAT) ? h[(size_t)u * FEAT + k] : 0.0f;
        __nv_bfloat16 hi = __float2bfloat16(a);
        __nv_bfloat16 lo = __float2bfloat16(a - __bfloat162float(hi));
        __nv_bfloat16* row = g_Abf + (size_t)u * KCAT;
        row[k] = hi; row[KSEG + k] = hi; row[2 * KSEG + k] = lo;
    } else if (idx < totA + totB) {
        int j = idx - totA;
        int i = j / KSEG, k = j - i * KSEG;
        float b = (k < FEAT) ? h[(size_t)(NUM_USERS + i) * FEAT + k] : 0.0f;
        if (k == 0) b = -b;  // sign fold
        __nv_bfloat16 hi = __float2bfloat16(b);
        __nv_bfloat16 lo = __float2bfloat16(b - __bfloat162float(hi));
        __nv_bfloat16* row = g_Bbf + (size_t)i * KCAT;
        row[k] = hi; row[KSEG + k] = lo; row[2 * KSEG + k] = hi;
    } else if (idx < totA + totB + totP) {
        int j = idx - totA - totB;
        int r = j / 16, k = 432 + (j - r * 16);
        __nv_bfloat16 z = __float2bfloat16(0.0f);
        if (r < NUM_USERS) g_Abf[(size_t)r * KCAT + k] = z;
        else g_Bbf[(size_t)(r - NUM_USERS) * KCAT + k] = z;
    }
}

// smem stage layout: A 16KB + B 32KB per stage, two stages = 96KB dynamic
#define ST_BYTES 49152
#define SB_OFF   16384
#define SM_SIZE  98304

__global__ __launch_bounds__(NTHREADS)
void gemm_mma_kernel(float* __restrict__ out) {
    extern __shared__ __align__(1024) char smem[];
    const uint32_t sb = smem_u32(smem);
    const int tid = threadIdx.x;
    const int wid = tid >> 5;
    const int L = tid & 31;
    const int m0 = blockIdx.x * BM;
    const int n0 = blockIdx.y * BN;
    const int mb = (wid & 1) * 64;    // warp m-offset (2 warps in m)
    const int nb = (wid >> 1) * 32;   // warp n-offset (8 warps in n)

    float acc[4][4][4];
    #pragma unroll
    for (int mi = 0; mi < 4; mi++)
        #pragma unroll
        for (int ni = 0; ni < 4; ni++)
            #pragma unroll
            for (int r = 0; r < 4; r++) acc[mi][ni][r] = 0.0f;

    // per-lane ldmatrix addressing invariants (SW128 swizzle: XOR = (row&7)*16)
    const uint32_t xorv = (L & 7) * 16;
    const uint32_t kha = (L >> 4) * 16;          // A: k-half from lane
    const uint32_t khb = ((L >> 3) & 1) * 16;    // B: k-half from lane
    uint32_t aBase[4], bBase[2];
    #pragma unroll
    for (int mi = 0; mi < 4; mi++)
        aBase[mi] = (uint32_t)(mb + mi * 16 + (L & 7) + ((L >> 3) & 1) * 8) * 128;
    #pragma unroll
    for (int p = 0; p < 2; p++)
        bBase[p] = (uint32_t)(nb + p * 16 + (L & 7) + ((L >> 4) & 1) * 8) * 128;

    // cooperative cp.async chunk loader (64 bf16 K-cols; A 128 rows, B 256 rows)
    auto load_chunk = [&](int c, int stg) {
        const uint32_t base = sb + stg * ST_BYTES;
        const size_t kbase = (size_t)c * BK;
        #pragma unroll
        for (int it = 0; it < 2; it++) {                 // A: 1024 x 16B
            int idx = tid + it * NTHREADS;
            int row = idx >> 3, k8 = idx & 7;
            const void* src = g_Abf + (size_t)(m0 + row) * KCAT + kbase + k8 * 8;
            uint32_t off = row * 128 + k8 * 16;
            uint32_t dst = base + (off ^ ((off >> 3) & 0x70));
            asm volatile("cp.async.cg.shared.global [%0], [%1], 16;" :: "r"(dst), "l"(src));
        }
        #pragma unroll
        for (int it = 0; it < 4; it++) {                 // B: 2048 x 16B
            int idx = tid + it * NTHREADS;
            int row = idx >> 3, k8 = idx & 7;
            const void* src = g_Bbf + (size_t)(n0 + row) * KCAT + kbase + k8 * 8;
            uint32_t off = row * 128 + k8 * 16;
            uint32_t dst = base + SB_OFF + (off ^ ((off >> 3) & 0x70));
            asm volatile("cp.async.cg.shared.global [%0], [%1], 16;" :: "r"(dst), "l"(src));
        }
        asm volatile("cp.async.commit_group;" ::: "memory");
    };

    load_chunk(0, 0);
    asm volatile("cp.async.wait_group 0;" ::: "memory");
    __syncthreads();

    for (int ch = 0; ch < KCHUNKS; ch++) {
        const int stg = ch & 1;
        if (ch + 1 < KCHUNKS) load_chunk(ch + 1, stg ^ 1);

        const uint32_t stA = sb + stg * ST_BYTES;
        const uint32_t stB = stA + SB_OFF;
        #pragma unroll
        for (int ks = 0; ks < 4; ks++) {
            uint32_t a[4][4];
            #pragma unroll
            for (int mi = 0; mi < 4; mi++) {
                uint32_t addr = stA + aBase[mi] + (((uint32_t)ks * 32 + kha) ^ xorv);
                asm volatile("ldmatrix.sync.aligned.m8n8.x4.shared.b16 {%0,%1,%2,%3}, [%4];"
                    : "=r"(a[mi][0]), "=r"(a[mi][1]), "=r"(a[mi][2]), "=r"(a[mi][3]) : "r"(addr));
            }
            uint32_t b[4][2];
            #pragma unroll
            for (int p = 0; p < 2; p++) {
                uint32_t addr = stB + bBase[p] + (((uint32_t)ks * 32 + khb) ^ xorv);
                asm volatile("ldmatrix.sync.aligned.m8n8.x4.shared.b16 {%0,%1,%2,%3}, [%4];"
                    : "=r"(b[2 * p][0]), "=r"(b[2 * p][1]), "=r"(b[2 * p + 1][0]), "=r"(b[2 * p + 1][1])
                    : "r"(addr));
            }
            #pragma unroll
            for (int mi = 0; mi < 4; mi++)
                #pragma unroll
                for (int ni = 0; ni < 4; ni++) {
                    asm volatile(
                        "mma.sync.aligned.m16n8k16.row.col.f32.bf16.bf16.f32 "
                        "{%0,%1,%2,%3}, {%4,%5,%6,%7}, {%8,%9}, {%0,%1,%2,%3};"
                        : "+f"(acc[mi][ni][0]), "+f"(acc[mi][ni][1]),
                          "+f"(acc[mi][ni][2]), "+f"(acc[mi][ni][3])
                        : "r"(a[mi][0]), "r"(a[mi][1]), "r"(a[mi][2]), "r"(a[mi][3]),
                          "r"(b[ni][0]), "r"(b[ni][1]));
                }
        }
        asm volatile("cp.async.wait_group 0;" ::: "memory");
        __syncthreads();
    }

    // ---- fused epilogue: theta=max(-d, 1+1e-7); out = -min(acosh(theta)^2, 50) ----
    const float THMIN = 1.00000011920928955f;  // fp32(1 + 1e-7), identical to jnp
    const float LN2 = 0.69314718055994531f;
    #pragma unroll
    for (int mi = 0; mi < 4; mi++) {
        const int r0 = m0 + mb + mi * 16 + (L >> 2);
        #pragma unroll
        for (int ni = 0; ni < 4; ni++) {
            const int col = n0 + nb + ni * 8 + (L & 3) * 2;
            float v[4];
            #pragma unroll
            for (int r = 0; r < 4; r++) {
                float th = fmaxf(-acc[mi][ni][r], THMIN);
                float x = fmaf(th, th, -1.0f);
                float sq; asm("sqrt.approx.f32 %0, %1;" : "=f"(sq) : "f"(x));
                float lg; asm("lg2.approx.f32 %0, %1;" : "=f"(lg) : "f"(th + sq));
                float s = lg * LN2;
                v[r] = -fminf(s * s, 50.0f);
            }
            *(float2*)(out + (size_t)r0 * NUM_ITEMS + col)       = make_float2(v[0], v[1]);
            *(float2*)(out + (size_t)(r0 + 8) * NUM_ITEMS + col) = make_float2(v[2], v[3]);
        }
    }
}

extern "C" void kernel_launch(void* const* d_in, const int* in_sizes, int n_in,
                              void* d_out, int out_size) {
    const float* h = (const float*)d_in[0];
    float* out = (float*)d_out;

    const int totPrep = (NUM_USERS + NUM_ITEMS) * KSEG + (NUM_USERS + NUM_ITEMS) * 16;
    prep_kernel<<<(totPrep + 255) / 256, 256>>>(h);

    cudaFuncSetAttribute(gemm_mma_kernel, cudaFuncAttributeMaxDynamicSharedMemorySize, SM_SIZE);
    dim3 grid(NUM_USERS / BM, NUM_ITEMS / BN);  // (64, 128)
    gemm_mma_kernel<<<grid, NTHREADS, SM_SIZE>>>(out);
}